// round 1
// baseline (speedup 1.0000x reference)
#include <cuda_runtime.h>

// ClassCaps: votes[b,h,w,i,o,m,p] = sum_n poses[b,h,w,i,m,n] * weight[i,o,n,p]
//            + (m==0,p==3)? xv[h,w] + (m==1,p==3)? yv[h,w]
// acts passthrough. Output = concat(votes.flatten(), acts.flatten()).
//
// B=64 H=14 W=14 CAPS_IN=32 O=10 A=4
// One thread per (b,h,w,i): loads 4x4 pose (4x LDG.128), weight staged in
// smem transposed to [o][n][i] so lane==i reads are conflict-free LDS.128,
// writes 10 * 64B contiguous chunks (40x STG.128). HBM-write-bound.

#define CB   64
#define CH   14
#define CW   14
#define CIN  32
#define CO   10
#define NTH  (CB*CH*CW*CIN)            // 401408 threads total
#define NV   ((long long)NTH * CO * 16) // 64225280 vote floats

__global__ __launch_bounds__(256) void classcaps_kernel(
    const float4* __restrict__ poses4,   // [NTH][4] float4 (rows m)
    const float*  __restrict__ acts,     // [NTH]
    const float4* __restrict__ wg4,      // [CIN*CO*4] float4, gmem layout i,o,n
    const float*  __restrict__ xv,       // [H*W]
    const float*  __restrict__ yv,       // [H*W]
    float4*       __restrict__ votes4,   // [NTH*40]
    float*        __restrict__ acts_out) // [NTH]
{
    // Stage weight into smem, transposed: wsm[(o*4+n)*32 + i]
    __shared__ float4 wsm[CO * 4 * CIN]; // 1280 float4 = 20KB
    const int t = threadIdx.x;
    #pragma unroll
    for (int j = t; j < CO * 4 * CIN; j += 256) {
        float4 v = wg4[j];
        int i   = j / (CO * 4);
        int rem = j % (CO * 4);        // o*4+n
        wsm[rem * CIN + i] = v;
    }
    __syncthreads();

    const int tid = blockIdx.x * 256 + t;   // exact: grid*block == NTH
    const int i   = tid & 31;               // == lane
    const int hw  = (tid >> 5) % (CH * CW); // h*W + w

    // Pose rows m=0..3, each a float4 over n. Fully coalesced: offset tid*4.
    const float4* prow = poses4 + (size_t)tid * 4;
    const float4 p0 = prow[0];
    const float4 p1 = prow[1];
    const float4 p2 = prow[2];
    const float4 p3 = prow[3];

    const float xvv = xv[hw];
    const float yvv = yv[hw];

    float4* outp = votes4 + (size_t)tid * (CO * 4);

    #pragma unroll
    for (int o = 0; o < CO; o++) {
        // weight rows n=0..3 for (i,o): consecutive-lane 16B -> conflict-free
        const float4* wp = &wsm[(o * 4) * CIN + i];
        const float4 w0 = wp[0 * CIN];
        const float4 w1 = wp[1 * CIN];
        const float4 w2 = wp[2 * CIN];
        const float4 w3 = wp[3 * CIN];

        float4 r;
        // m = 0
        r.x = p0.x*w0.x + p0.y*w1.x + p0.z*w2.x + p0.w*w3.x;
        r.y = p0.x*w0.y + p0.y*w1.y + p0.z*w2.y + p0.w*w3.y;
        r.z = p0.x*w0.z + p0.y*w1.z + p0.z*w2.z + p0.w*w3.z;
        r.w = p0.x*w0.w + p0.y*w1.w + p0.z*w2.w + p0.w*w3.w + xvv;
        outp[o * 4 + 0] = r;
        // m = 1
        r.x = p1.x*w0.x + p1.y*w1.x + p1.z*w2.x + p1.w*w3.x;
        r.y = p1.x*w0.y + p1.y*w1.y + p1.z*w2.y + p1.w*w3.y;
        r.z = p1.x*w0.z + p1.y*w1.z + p1.z*w2.z + p1.w*w3.z;
        r.w = p1.x*w0.w + p1.y*w1.w + p1.z*w2.w + p1.w*w3.w + yvv;
        outp[o * 4 + 1] = r;
        // m = 2
        r.x = p2.x*w0.x + p2.y*w1.x + p2.z*w2.x + p2.w*w3.x;
        r.y = p2.x*w0.y + p2.y*w1.y + p2.z*w2.y + p2.w*w3.y;
        r.z = p2.x*w0.z + p2.y*w1.z + p2.z*w2.z + p2.w*w3.z;
        r.w = p2.x*w0.w + p2.y*w1.w + p2.z*w2.w + p2.w*w3.w;
        outp[o * 4 + 2] = r;
        // m = 3
        r.x = p3.x*w0.x + p3.y*w1.x + p3.z*w2.x + p3.w*w3.x;
        r.y = p3.x*w0.y + p3.y*w1.y + p3.z*w2.y + p3.w*w3.y;
        r.z = p3.x*w0.z + p3.y*w1.z + p3.z*w2.z + p3.w*w3.z;
        r.w = p3.x*w0.w + p3.y*w1.w + p3.z*w2.w + p3.w*w3.w;
        outp[o * 4 + 3] = r;
    }

    // acts output shares the same linear index
    acts_out[tid] = acts[tid];
}

extern "C" void kernel_launch(void* const* d_in, const int* in_sizes, int n_in,
                              void* d_out, int out_size) {
    const float4* poses4 = (const float4*)d_in[0];
    const float*  acts   = (const float*)d_in[1];
    const float4* wg4    = (const float4*)d_in[2];
    const float*  xv     = (const float*)d_in[3];
    const float*  yv     = (const float*)d_in[4];
    float* out = (float*)d_out;

    classcaps_kernel<<<NTH / 256, 256>>>(poses4, acts, wg4, xv, yv,
                                         (float4*)out, out + NV);
}

// round 4
// speedup vs baseline: 2.2947x; 2.2947x over previous
#include <cuda_runtime.h>

// ClassCaps: votes[b,h,w,i,o,m,p] = sum_n poses[b,h,w,i,m,n] * weight[i,o,n,p]
//            + (m==0,p==3)? xv[h,w] ; + (m==1,p==3)? yv[h,w]
// acts passthrough. Output = concat(votes.flatten(), acts.flatten()).
//
// R4: thread per (capsule, m). Warp = 8 capsules x 4 m (m fastest) so each
// STG.128 writes 8 contiguous 64B chunks (8 wavefronts vs 32 in R1 -> 4x less
// L1 store pressure, the R1 bottleneck). Streaming stores via __stcs.
// No inline asm (v8 ld/st suspected of killing the R2/R3 runs).

#define CB   64
#define CH   14
#define CW   14
#define CIN  32
#define CO   10
#define NCAP (CB*CH*CW*CIN)               // 401408 capsules
#define NTH  (NCAP*4)                     // 1605632 threads
#define NV   ((long long)NCAP * CO * 16)  // 64225280 vote floats

__global__ __launch_bounds__(256, 6) void classcaps_kernel(
    const float4* __restrict__ poses4,   // [NCAP*4] float4 (rows m)
    const float*  __restrict__ acts,     // [NCAP]
    const float4* __restrict__ wg4,      // [CIN*CO*4] float4, gmem layout i,o,n
    const float*  __restrict__ xv,       // [H*W]
    const float*  __restrict__ yv,       // [H*W]
    float4*       __restrict__ votes4,   // [NCAP*40]
    float*        __restrict__ acts_out) // [NCAP]
{
    // Stage weight into smem, transposed: wsm[(o*4+n)*32 + i], float4 over p
    __shared__ float4 wsm[CO * 4 * CIN]; // 1280 float4 = 20KB
    const int t = threadIdx.x;
    for (int j = t; j < CO * 4 * CIN; j += 256) {
        float4 v = wg4[j];
        int i   = j / (CO * 4);
        int rem = j % (CO * 4);        // o*4+n
        wsm[rem * CIN + i] = v;
    }
    __syncthreads();

    const int tid = blockIdx.x * 256 + t;   // exact: grid*block == NTH
    const int m   = tid & 3;
    const int cap = tid >> 2;               // capsule index (b,h,w,i)
    const int i   = cap & 31;               // caps_in index
    const int hw  = (cap >> 5) % (CH * CW); // h*W + w

    // Pose row m for this capsule: one perfectly coalesced float4 load.
    const float4 pv = poses4[tid];

    // coordinate add: (m==0,p==3)+=xv ; (m==1,p==3)+=yv
    float addw = 0.0f;
    if (m == 0) addw = xv[hw];
    else if (m == 1) addw = yv[hw];

    float4* outp = votes4 + (size_t)cap * (CO * 4) + m;

    #pragma unroll
    for (int o = 0; o < CO; o++) {
        // weight rows n=0..3 for (i,o): 8 consecutive i per warp, 4-lane
        // broadcast over m -> conflict-free LDS.128
        const float4* wp = &wsm[(o * 4) * CIN + i];
        const float4 w0 = wp[0 * CIN];
        const float4 w1 = wp[1 * CIN];
        const float4 w2 = wp[2 * CIN];
        const float4 w3 = wp[3 * CIN];

        float4 r;
        r.x = pv.x*w0.x + pv.y*w1.x + pv.z*w2.x + pv.w*w3.x;
        r.y = pv.x*w0.y + pv.y*w1.y + pv.z*w2.y + pv.w*w3.y;
        r.z = pv.x*w0.z + pv.y*w1.z + pv.z*w2.z + pv.w*w3.z;
        r.w = pv.x*w0.w + pv.y*w1.w + pv.z*w2.w + pv.w*w3.w + addw;
        __stcs(outp + o * 4, r);   // streaming: evict-first in L2
    }

    // acts passthrough: one lane per capsule
    if (m == 0) acts_out[cap] = acts[cap];
}

extern "C" void kernel_launch(void* const* d_in, const int* in_sizes, int n_in,
                              void* d_out, int out_size) {
    const float4* poses4 = (const float4*)d_in[0];
    const float*  acts   = (const float*)d_in[1];
    const float4* wg4    = (const float4*)d_in[2];
    const float*  xv     = (const float*)d_in[3];
    const float*  yv     = (const float*)d_in[4];
    float* out = (float*)d_out;

    classcaps_kernel<<<NTH / 256, 256>>>(poses4, acts, wg4, xv, yv,
                                         (float4*)out, out + NV);
}

// round 5
// speedup vs baseline: 2.4263x; 1.0574x over previous
#include <cuda_runtime.h>

// ClassCaps: votes[b,h,w,i,o,m,p] = sum_n poses[b,h,w,i,m,n] * weight[i,o,n,p]
//            + (m==0,p==3)? xv[h,w] ; + (m==1,p==3)? yv[h,w]
// acts passthrough. Output = concat(votes.flatten(), acts.flatten()).
//
// R5: thread per (capsule, o_lo, m); warp = 4 caps x 2 o_lo x 4 m. Each store
// instruction writes 128B contiguous per capsule -> 5 line-touches per
// capsule (the minimum), halving R4's store-side L1 wavefronts.
// Weights staged in smem as [n][o][i] padded to 36 -> conflict-free LDS.128
// for the (4 i x 2 o) lane pattern.

#define CB   64
#define CH   14
#define CW   14
#define CIN  32
#define CO   10
#define NCAP (CB*CH*CW*CIN)               // 401408 capsules
#define NTH  (NCAP*8)                     // 3211264 threads
#define NV   ((long long)NCAP * CO * 16)  // 64225280 vote floats
#define WP   36                           // padded i-stride (float4 units)

__global__ __launch_bounds__(256, 6) void classcaps_kernel(
    const float4* __restrict__ poses4,   // [NCAP*4] float4 (rows m)
    const float*  __restrict__ acts,     // [NCAP]
    const float4* __restrict__ wg4,      // [CIN*CO*4] float4, gmem layout i,o,n
    const float*  __restrict__ xv,       // [H*W]
    const float*  __restrict__ yv,       // [H*W]
    float4*       __restrict__ votes4,   // [NCAP*40]
    float*        __restrict__ acts_out) // [NCAP]
{
    // Stage weight into smem: wsm[(n*CO + o)*WP + i], float4 over p.
    __shared__ float4 wsm[4 * CO * WP];  // 1440 float4 = 22.5KB
    const int t = threadIdx.x;
    for (int j = t; j < CIN * CO * 4; j += 256) {
        float4 v = wg4[j];
        int i = j / (CO * 4);
        int o = (j % (CO * 4)) >> 2;
        int n = j & 3;
        wsm[(n * CO + o) * WP + i] = v;
    }
    __syncthreads();

    const int tid  = blockIdx.x * 256 + t;  // exact: grid*block == NTH
    const int m    = tid & 3;
    const int olo  = (tid >> 2) & 1;
    const int cap  = tid >> 3;              // capsule index (b,h,w,i)
    const int i    = cap & 31;              // caps_in index
    const int hw   = (cap >> 5) % (CH * CW);

    // Pose row m for this capsule (warp: 16 distinct float4, 2 lines, bcast).
    const float4 pv = poses4[cap * 4 + m];

    // coordinate add: (m==0,p==3)+=xv ; (m==1,p==3)+=yv
    float addw = 0.0f;
    if (m == 0) addw = xv[hw];
    else if (m == 1) addw = yv[hw];

    float4* outp = votes4 + (size_t)cap * (CO * 4) + m;

    #pragma unroll
    for (int oo = 0; oo < 5; oo++) {
        const int o = 2 * oo + olo;
        const float4* wp = &wsm[o * WP + i];
        const float4 w0 = wp[0 * CO * WP];
        const float4 w1 = wp[1 * CO * WP];
        const float4 w2 = wp[2 * CO * WP];
        const float4 w3 = wp[3 * CO * WP];

        float4 r;
        r.x = pv.x*w0.x + pv.y*w1.x + pv.z*w2.x + pv.w*w3.x;
        r.y = pv.x*w0.y + pv.y*w1.y + pv.z*w2.y + pv.w*w3.y;
        r.z = pv.x*w0.z + pv.y*w1.z + pv.z*w2.z + pv.w*w3.z;
        r.w = pv.x*w0.w + pv.y*w1.w + pv.z*w2.w + pv.w*w3.w + addw;
        __stcs(outp + o * 4, r);   // warp: 4 caps x 128B contiguous = 4 lines
    }

    // acts passthrough: one lane per capsule
    if ((tid & 7) == 0) acts_out[cap] = acts[cap];
}

extern "C" void kernel_launch(void* const* d_in, const int* in_sizes, int n_in,
                              void* d_out, int out_size) {
    const float4* poses4 = (const float4*)d_in[0];
    const float*  acts   = (const float*)d_in[1];
    const float4* wg4    = (const float4*)d_in[2];
    const float*  xv     = (const float*)d_in[3];
    const float*  yv     = (const float*)d_in[4];
    float* out = (float*)d_out;

    classcaps_kernel<<<NTH / 256, 256>>>(poses4, acts, wg4, xv, yv,
                                         (float4*)out, out + NV);
}

// round 8
// speedup vs baseline: 3.2004x; 1.3190x over previous
#include <cuda_runtime.h>

// ClassCaps: votes[b,h,w,i,o,m,p] = sum_n poses[b,h,w,i,m,n] * weight[i,o,n,p]
//            + (m==0,p==3)? xv[h,w] ; + (m==1,p==3)? yv[h,w]
// acts passthrough. Output = concat(votes.flatten(), acts.flatten()).
//
// R8 (= R6/R7 algorithm, de-risked structure): warp = 4 caps (same i,
// stride-32) x 2 o_lo x 4 m; each thread owns K=4 capsules. o-loop outer,
// capsule-loop inner -> each weight LDS amortized over 4 capsules
// (L1 wavefronts/capsule ~26 -> ~11). Stores stay 128B-contiguous per
// capsule. Changes vs R7: default launch bounds, uniform (non-divergent)
// acts passthrough handled by the low blocks.

#define CB   64
#define CH   14
#define CW   14
#define CIN  32
#define CO   10
#define NCAP (CB*CH*CW*CIN)               // 401408 capsules
#define KC   4                            // capsules per thread
#define NTH  (NCAP*8/KC)                  // 802816 threads
#define NBLK (NTH/256)                    // 3136 blocks
#define NV   ((long long)NCAP * CO * 16)  // 64225280 vote floats
#define WP   36                           // padded i-stride (float4 units)
#define ACTS_BLKS ((NCAP + 8191) / 8192)  // 49 blocks cover acts at 32/thread? no: see below

__global__ __launch_bounds__(256) void classcaps_kernel(
    const float4* __restrict__ poses4,   // [NCAP*4] float4 (rows m)
    const float*  __restrict__ acts,     // [NCAP]
    const float4* __restrict__ wg4,      // [CIN*CO*4] float4, gmem layout i,o,n
    const float*  __restrict__ xv,       // [H*W]
    const float*  __restrict__ yv,       // [H*W]
    float4*       __restrict__ votes4,   // [NCAP*40]
    float*        __restrict__ acts_out) // [NCAP]
{
    // Stage weight into smem: wsm[(n*CO + o)*WP + i], float4 over p.
    __shared__ float4 wsm[4 * CO * WP];  // 1440 float4 = 22.5KB
    const int t = threadIdx.x;
    for (int j = t; j < CIN * CO * 4; j += 256) {
        float4 v = wg4[j];
        int iw = j / (CO * 4);
        int ow = (j % (CO * 4)) >> 2;
        int nw = j & 3;
        wsm[(nw * CO + ow) * WP + iw] = v;
    }

    // acts passthrough: flat coalesced copy, first NCAP/(256*2) blocks do
    // 2 elements each; uniform control flow (no lane divergence).
    {
        const int g = blockIdx.x * 256 + t;
        if (g * 2 + 1 < NCAP) {
            float2 a = ((const float2*)acts)[g];
            ((float2*)acts_out)[g] = a;
        }
    }
    __syncthreads();

    const int lane   = t & 31;
    const int m      = lane & 3;
    const int olo    = (lane >> 2) & 1;
    const int capsel = (lane >> 3) & 3;
    const int Wg     = blockIdx.x * 8 + (t >> 5);   // global warp id
    const int i      = Wg & 31;                     // caps_in (fixed per warp)
    const int qblk   = Wg >> 5;                     // 0..783
    const int q0     = qblk * (4 * KC) + capsel;    // base q for this lane

    // Preload K poses, coord-adds, output offsets (branch-free).
    float4 pv[KC];
    float  addw[KC];
    int    off[KC];                                 // float4 index of (cap, m)
    #pragma unroll
    for (int k = 0; k < KC; k++) {
        const int q   = q0 + k * 4;
        const int cap = q * 32 + i;
        pv[k]  = poses4[cap * 4 + m];
        const int hw = q % (CH * CW);
        const float cx = xv[hw], cy = yv[hw];
        addw[k] = (m == 0) ? cx : ((m == 1) ? cy : 0.0f);
        off[k]  = cap * (CO * 4) + m;
    }

    #pragma unroll
    for (int oo = 0; oo < 5; oo++) {
        const int o = 2 * oo + olo;
        // weight rows n=0..3 for (i,o): 2 distinct addrs/warp -> broadcast LDS
        const float4* wp = &wsm[o * WP + i];
        const float4 w0 = wp[0 * CO * WP];
        const float4 w1 = wp[1 * CO * WP];
        const float4 w2 = wp[2 * CO * WP];
        const float4 w3 = wp[3 * CO * WP];

        #pragma unroll
        for (int k = 0; k < KC; k++) {
            const float4 p = pv[k];
            float4 r;
            r.x = p.x*w0.x + p.y*w1.x + p.z*w2.x + p.w*w3.x;
            r.y = p.x*w0.y + p.y*w1.y + p.z*w2.y + p.w*w3.y;
            r.z = p.x*w0.z + p.y*w1.z + p.z*w2.z + p.w*w3.z;
            r.w = p.x*w0.w + p.y*w1.w + p.z*w2.w + p.w*w3.w + addw[k];
            __stcs(votes4 + off[k] + o * 4, r);  // 4 caps x 128B contig/instr
        }
    }
}

extern "C" void kernel_launch(void* const* d_in, const int* in_sizes, int n_in,
                              void* d_out, int out_size) {
    const float4* poses4 = (const float4*)d_in[0];
    const float*  acts   = (const float*)d_in[1];
    const float4* wg4    = (const float4*)d_in[2];
    const float*  xv     = (const float*)d_in[3];
    const float*  yv     = (const float*)d_in[4];
    float* out = (float*)d_out;

    classcaps_kernel<<<NBLK, 256>>>(poses4, acts, wg4, xv, yv,
                                    (float4*)out, out + NV);
}